// round 6
// baseline (speedup 1.0000x reference)
#include <cuda_runtime.h>

#define Bb 64
#define Tt 512
#define Ii 128
#define Hh 1024
#define Ll 4
#define Oo 128
#define Mm (Bb * Tt)   // 32768

#define SCAN_NBLK 128  // 32 j-tiles x 4 b-tiles, 1 CTA/SM -> co-resident

// packed fp32 pair FMA: d.lo = a.lo*b.lo + c.lo ; d.hi = a.hi*b.hi + c.hi
#define FFMA2(d, a, b, c) \
    asm("fma.rn.f32x2 %0, %1, %2, %3;" : "=l"(d) : "l"(a), "l"(b), "l"(c))

// Scratch: input projections and layer output / hidden-state history.
// g_out[b][t][h] holds h_t for the layer being scanned; step t reads row t-1.
__device__ float g_xin[(size_t)Bb * Tt * Hh];
__device__ float g_out[(size_t)Bb * Tt * Hh];

// Software grid barrier. count returns to 0 after each use; phase is monotonic
// and compared against a locally captured snapshot -> safe across graph
// replays. The wait is BOUNDED (~20ms) so a residency/scheduling surprise
// degrades to a measurable wrong answer instead of a hung container.
__device__ unsigned g_bar_count;
__device__ volatile unsigned g_bar_phase;

__device__ __forceinline__ void grid_barrier()
{
    __threadfence();
    __syncthreads();
    if (threadIdx.x == 0) {
        const unsigned old = g_bar_phase;
        if (atomicAdd(&g_bar_count, 1u) == SCAN_NBLK - 1) {
            g_bar_count = 0;
            __threadfence();
            g_bar_phase = old + 1;
        } else {
            const long long t0 = clock64();
            while (g_bar_phase == old) {
                __nanosleep(64);
                if (clock64() - t0 > 40000000LL) break;   // escape hatch
            }
        }
        __threadfence();
    }
    __syncthreads();
}

// ---------------------------------------------------------------------------
// GEMM: C[M,N] = A[M,K] @ W[N,K]^T + b1[N] (+ b2[N])
// 256 threads, 128x128 tile, BK=16, 8x8 micro-tile, register-prefetch.
// ---------------------------------------------------------------------------
#define GBM 128
#define GBN 128
#define GBK 16

__global__ __launch_bounds__(256, 1) void gemm_bias_kernel(
    const float* __restrict__ A, const float* __restrict__ W,
    const float* __restrict__ b1, const float* __restrict__ b2,
    float* __restrict__ C, int M, int N, int K)
{
    __shared__ __align__(16) float As[GBK][GBM + 4];
    __shared__ __align__(16) float Ws[GBK][GBN + 4];

    const int bm = blockIdx.x * GBM;
    const int bn = blockIdx.y * GBN;
    const int tid = threadIdx.x;
    const int tx = tid & 15;
    const int ty = tid >> 4;

    float acc[8][8];
#pragma unroll
    for (int i = 0; i < 8; i++)
#pragma unroll
        for (int j = 0; j < 8; j++) acc[i][j] = 0.f;

    const int r0 = tid >> 2;
    const int r1 = r0 + 64;
    const int c4 = tid & 3;

    const float* arow0 = A + (size_t)(bm + r0) * K + c4 * 4;
    const float* arow1 = A + (size_t)(bm + r1) * K + c4 * 4;
    const float* wrow0 = W + (size_t)(bn + r0) * K + c4 * 4;
    const float* wrow1 = W + (size_t)(bn + r1) * K + c4 * 4;

    float4 pa0 = *(const float4*)arow0;
    float4 pa1 = *(const float4*)arow1;
    float4 pw0 = *(const float4*)wrow0;
    float4 pw1 = *(const float4*)wrow1;

    const int nkb = K / GBK;
    for (int kb = 0; kb < nkb; kb++) {
        As[c4 * 4 + 0][r0] = pa0.x; As[c4 * 4 + 1][r0] = pa0.y;
        As[c4 * 4 + 2][r0] = pa0.z; As[c4 * 4 + 3][r0] = pa0.w;
        As[c4 * 4 + 0][r1] = pa1.x; As[c4 * 4 + 1][r1] = pa1.y;
        As[c4 * 4 + 2][r1] = pa1.z; As[c4 * 4 + 3][r1] = pa1.w;
        Ws[c4 * 4 + 0][r0] = pw0.x; Ws[c4 * 4 + 1][r0] = pw0.y;
        Ws[c4 * 4 + 2][r0] = pw0.z; Ws[c4 * 4 + 3][r0] = pw0.w;
        Ws[c4 * 4 + 0][r1] = pw1.x; Ws[c4 * 4 + 1][r1] = pw1.y;
        Ws[c4 * 4 + 2][r1] = pw1.z; Ws[c4 * 4 + 3][r1] = pw1.w;
        __syncthreads();

        if (kb + 1 < nkb) {
            const int k = (kb + 1) * GBK;
            pa0 = *(const float4*)(arow0 + k);
            pa1 = *(const float4*)(arow1 + k);
            pw0 = *(const float4*)(wrow0 + k);
            pw1 = *(const float4*)(wrow1 + k);
        }

#pragma unroll
        for (int kk = 0; kk < GBK; kk++) {
            float4 a0 = *(const float4*)&As[kk][ty * 8];
            float4 a1 = *(const float4*)&As[kk][ty * 8 + 4];
            float4 w0 = *(const float4*)&Ws[kk][tx * 8];
            float4 w1 = *(const float4*)&Ws[kk][tx * 8 + 4];
            const float av[8] = {a0.x, a0.y, a0.z, a0.w, a1.x, a1.y, a1.z, a1.w};
            const float wv[8] = {w0.x, w0.y, w0.z, w0.w, w1.x, w1.y, w1.z, w1.w};
#pragma unroll
            for (int i = 0; i < 8; i++)
#pragma unroll
                for (int j = 0; j < 8; j++) acc[i][j] += av[i] * wv[j];
        }
        __syncthreads();
    }

    float bias[8];
#pragma unroll
    for (int j = 0; j < 8; j++) bias[j] = b1[bn + tx * 8 + j];
    if (b2 != nullptr) {
#pragma unroll
        for (int j = 0; j < 8; j++) bias[j] += b2[bn + tx * 8 + j];
    }
#pragma unroll
    for (int i = 0; i < 8; i++) {
        const size_t row = (size_t)(bm + ty * 8 + i) * N + bn + tx * 8;
        float4 s0 = make_float4(acc[i][0] + bias[0], acc[i][1] + bias[1],
                                acc[i][2] + bias[2], acc[i][3] + bias[3]);
        float4 s1 = make_float4(acc[i][4] + bias[4], acc[i][5] + bias[5],
                                acc[i][6] + bias[6], acc[i][7] + bias[7]);
        *(float4*)&C[row] = s0;
        *(float4*)&C[row + 4] = s1;
    }
}

// ---------------------------------------------------------------------------
// Persistent recurrence scan for one layer (all T steps in one launch).
//   g_out[b,t,j] = relu(g_xin[b,t,j] + sum_k h_prev[b,k] * Whh[j,k])
// Grid (32, 4): CTA tile = 16 batch x 32 cols, 128 threads.
// Per-thread 2b x 2j micro-tile computed with fma.rn.f32x2 packed over k.
// Smem (dynamic, 192.5 KB):
//   Ws[32][1028]  : CTA's Whh slice, K-major (resident whole layer)
//   Hs[256][64]   : h_prev tile [k4][phase=b&1][slot^(k4&7)][4], restaged/step
// ---------------------------------------------------------------------------
#define WS_STRIDE 1028
#define WS_FLOATS (32 * WS_STRIDE)
#define HS_FLOATS (256 * 64)
#define SCAN_SMEM ((WS_FLOATS + HS_FLOATS) * (int)sizeof(float))

__global__ __launch_bounds__(128, 1) void rnn_scan_kernel(
    const float* __restrict__ Whh, const float* __restrict__ hid,
    float* __restrict__ hn)
{
    extern __shared__ float sm[];
    float* Ws = sm;                 // [32][WS_STRIDE]
    float* Hs = sm + WS_FLOATS;     // [256][64]

    const int jb  = blockIdx.x * 32;
    const int bb  = blockIdx.y * 16;
    const int tid = threadIdx.x;
    const int wid  = tid >> 5;
    const int lane = tid & 31;
    const int ty   = lane >> 2;     // 0..7 : b-pair (b0 = 2*ty)
    const int txw  = lane & 3;      // 0..3 : j-pair within warp's 8 cols
    const int jloc = wid * 8 + txw * 2;
    const int b0l  = ty * 2;

    // One-time: copy this CTA's Whh slice (K-major, padded rows).
#pragma unroll 4
    for (int idx = tid; idx < 32 * 256; idx += 128) {
        const int j = idx >> 8, k4 = idx & 255;
        float4 w = *(const float4*)&Whh[(size_t)(jb + j) * Hh + k4 * 4];
        *(float4*)&Ws[j * WS_STRIDE + k4 * 4] = w;
    }
    __syncthreads();

    const float* wrow0 = Ws + jloc * WS_STRIDE;
    const float* wrow1 = wrow0 + WS_STRIDE;

    for (int t = 0; t < Tt; t++) {
        // ---- stage h_prev tile (16 x 1024) into swizzled smem ----
        const float* hsrc;
        size_t bstride;
        if (t == 0) { hsrc = hid + (size_t)bb * Hh;                    bstride = Hh; }
        else        { hsrc = g_out + ((size_t)bb * Tt + (t - 1)) * Hh; bstride = (size_t)Tt * Hh; }

#pragma unroll 8
        for (int i = 0; i < 32; i++) {
            const int fid = i * 128 + tid;
            const int b  = fid >> 8;       // 0..15
            const int k4 = fid & 255;      // 0..255
            float4 h4 = *(const float4*)&hsrc[(size_t)b * bstride + k4 * 4];
            const int slot = (b >> 1) ^ (k4 & 7);
            *(float4*)&Hs[k4 * 64 + (b & 1) * 32 + slot * 4] = h4;
        }
        __syncthreads();

        // ---- accumulate: packed-over-k 2x2 outer product ----
        unsigned long long acc[8];
#pragma unroll
        for (int i = 0; i < 8; i++) acc[i] = 0ULL;   // (+0.f, +0.f)

#pragma unroll 8
        for (int k4 = 0; k4 < 256; k4++) {
            const int slot = ty ^ (k4 & 7);
            const float* ap = Hs + k4 * 64 + slot * 4;
            ulonglong2 a0 = *(const ulonglong2*)ap;          // h[b0][4k..4k+3]
            ulonglong2 a1 = *(const ulonglong2*)(ap + 32);   // h[b0+1][...]
            ulonglong2 w0 = *(const ulonglong2*)(wrow0 + k4 * 4);
            ulonglong2 w1 = *(const ulonglong2*)(wrow1 + k4 * 4);
            FFMA2(acc[0], a0.x, w0.x, acc[0]);
            FFMA2(acc[1], a0.y, w0.y, acc[1]);
            FFMA2(acc[2], a0.x, w1.x, acc[2]);
            FFMA2(acc[3], a0.y, w1.y, acc[3]);
            FFMA2(acc[4], a1.x, w0.x, acc[4]);
            FFMA2(acc[5], a1.y, w0.y, acc[5]);
            FFMA2(acc[6], a1.x, w1.x, acc[6]);
            FFMA2(acc[7], a1.y, w1.y, acc[7]);
        }

        // ---- horizontal reduce, add xin, relu, store ----
        float2 p[8];
#pragma unroll
        for (int i = 0; i < 8; i++) p[i] = *(float2*)&acc[i];
        const float v00 = (p[0].x + p[0].y) + (p[1].x + p[1].y);
        const float v01 = (p[2].x + p[2].y) + (p[3].x + p[3].y);
        const float v10 = (p[4].x + p[4].y) + (p[5].x + p[5].y);
        const float v11 = (p[6].x + p[6].y) + (p[7].x + p[7].y);

        const int b0g = bb + b0l;
        const int j0g = jb + jloc;
        const size_t base0 = ((size_t)b0g * Tt + t) * Hh + j0g;
        const size_t base1 = base0 + (size_t)Tt * Hh;

        float2 x0 = *(const float2*)&g_xin[base0];
        float2 x1 = *(const float2*)&g_xin[base1];
        float2 o0 = make_float2(fmaxf(v00 + x0.x, 0.f), fmaxf(v01 + x0.y, 0.f));
        float2 o1 = make_float2(fmaxf(v10 + x1.x, 0.f), fmaxf(v11 + x1.y, 0.f));
        *(float2*)&g_out[base0] = o0;
        *(float2*)&g_out[base1] = o1;

        if (t == Tt - 1) {   // h_n for this layer
            *(float2*)&hn[(size_t)b0g * Hh + j0g]       = o0;
            *(float2*)&hn[(size_t)(b0g + 1) * Hh + j0g] = o1;
        }

        grid_barrier();
    }
}

// ---------------------------------------------------------------------------
extern "C" void kernel_launch(void* const* d_in, const int* in_sizes, int n_in,
                              void* d_out, int out_size)
{
    const float* x      = (const float*)d_in[0];
    const float* hidden = (const float*)d_in[1];
    const float* Wih0   = (const float*)d_in[2];
    const float* Whh0   = (const float*)d_in[3];
    const float* bih0   = (const float*)d_in[4];
    const float* bhh0   = (const float*)d_in[5];
    const float* WihL   = (const float*)d_in[6];
    const float* WhhL   = (const float*)d_in[7];
    const float* bihL   = (const float*)d_in[8];
    const float* bhhL   = (const float*)d_in[9];
    const float* Wfc    = (const float*)d_in[10];
    const float* bfc    = (const float*)d_in[11];
    float* out = (float*)d_out;

    float *xin_p = nullptr, *out_p = nullptr;
    cudaGetSymbolAddress((void**)&xin_p, g_xin);
    cudaGetSymbolAddress((void**)&out_p, g_out);

    cudaFuncSetAttribute(rnn_scan_kernel,
                         cudaFuncAttributeMaxDynamicSharedMemorySize, SCAN_SMEM);

    const dim3 projGrid(Mm / GBM, Hh / GBN);   // 256 x 8
    const dim3 scanGrid(Hh / 32, Bb / 16);     // 32 x 4 = 128 CTAs (1/SM)
    float* hn_base = out + (size_t)Bb * Tt * Oo;

    for (int l = 0; l < Ll; l++) {
        const float *Wih, *Whh, *bi, *bh;
        if (l == 0) { Wih = Wih0; Whh = Whh0; bi = bih0; bh = bhh0; }
        else {
            Wih = WihL + (size_t)(l - 1) * Hh * Hh;
            Whh = WhhL + (size_t)(l - 1) * Hh * Hh;
            bi  = bihL + (size_t)(l - 1) * Hh;
            bh  = bhhL + (size_t)(l - 1) * Hh;
        }

        // time-parallel input projection: g_xin = in @ Wih^T + b_ih + b_hh
        if (l == 0)
            gemm_bias_kernel<<<projGrid, 256>>>(x,     Wih, bi, bh, xin_p, Mm, Hh, Ii);
        else
            gemm_bias_kernel<<<projGrid, 256>>>(out_p, Wih, bi, bh, xin_p, Mm, Hh, Hh);

        // persistent scan: all 512 steps in one launch
        rnn_scan_kernel<<<scanGrid, 128, SCAN_SMEM>>>(
            Whh, hidden + (size_t)l * Bb * Hh, hn_base + (size_t)l * Bb * Hh);
    }

    // output projection: out = g_out @ W_fc^T + b_fc
    gemm_bias_kernel<<<dim3(Mm / GBM, Oo / GBN), 256>>>(out_p, Wfc, bfc, nullptr,
                                                        out, Mm, Oo, Hh);
}

// round 7
// speedup vs baseline: 1.0015x; 1.0015x over previous
#include <cuda_runtime.h>

#define Bb 64
#define Tt 512
#define Ii 128
#define Hh 1024
#define Ll 4
#define Oo 128
#define Mm (Bb * Tt)   // 32768

#define NGROUP 4       // independent batch-groups (16 b-rows each)
#define GRP_NBLK 32    // CTAs per group barrier (the j-tiles)

// packed fp32 pair FMA: d.lo = a.lo*b.lo + c.lo ; d.hi = a.hi*b.hi + c.hi
#define FFMA2(d, a, b, c) \
    asm("fma.rn.f32x2 %0, %1, %2, %3;" : "=l"(d) : "l"(a), "l"(b), "l"(c))

// Scratch: input projections and layer output / hidden-state history.
// g_out[b][t][h] holds h_t for the layer being scanned; step t reads row t-1.
__device__ float g_xin[(size_t)Bb * Tt * Hh];
__device__ float g_out[(size_t)Bb * Tt * Hh];

// Per-group software barrier. count returns to 0 after each use; phase is
// monotonic and compared to a locally captured snapshot -> safe across graph
// replays. Spin is bounded (~22ms) so any residency surprise degrades to a
// measurable wrong answer instead of a hung container.
__device__ unsigned g_bar_count[NGROUP];
__device__ volatile unsigned g_bar_phase[NGROUP];

__device__ __forceinline__ void group_barrier(int g)
{
    __threadfence();
    __syncthreads();
    if (threadIdx.x == 0) {
        const unsigned old = g_bar_phase[g];
        if (atomicAdd(&g_bar_count[g], 1u) == GRP_NBLK - 1) {
            g_bar_count[g] = 0;
            __threadfence();
            g_bar_phase[g] = old + 1;
        } else {
            const long long t0 = clock64();
            while (g_bar_phase[g] == old) {
                if (clock64() - t0 > 40000000LL) break;   // escape hatch
            }
        }
        __threadfence();
    }
    __syncthreads();
}

// ---------------------------------------------------------------------------
// GEMM: C[M,N] = A[M,K] @ W[N,K]^T + b1[N] (+ b2[N])
// 256 threads, 128x128 tile, BK=16, 8x8 micro-tile, register-prefetch.
// (measured at ~fp32 chip ceiling; tensor-core version is the next round)
// ---------------------------------------------------------------------------
#define GBM 128
#define GBN 128
#define GBK 16

__global__ __launch_bounds__(256, 1) void gemm_bias_kernel(
    const float* __restrict__ A, const float* __restrict__ W,
    const float* __restrict__ b1, const float* __restrict__ b2,
    float* __restrict__ C, int M, int N, int K)
{
    __shared__ __align__(16) float As[GBK][GBM + 4];
    __shared__ __align__(16) float Ws[GBK][GBN + 4];

    const int bm = blockIdx.x * GBM;
    const int bn = blockIdx.y * GBN;
    const int tid = threadIdx.x;
    const int tx = tid & 15;
    const int ty = tid >> 4;

    float acc[8][8];
#pragma unroll
    for (int i = 0; i < 8; i++)
#pragma unroll
        for (int j = 0; j < 8; j++) acc[i][j] = 0.f;

    const int r0 = tid >> 2;
    const int r1 = r0 + 64;
    const int c4 = tid & 3;

    const float* arow0 = A + (size_t)(bm + r0) * K + c4 * 4;
    const float* arow1 = A + (size_t)(bm + r1) * K + c4 * 4;
    const float* wrow0 = W + (size_t)(bn + r0) * K + c4 * 4;
    const float* wrow1 = W + (size_t)(bn + r1) * K + c4 * 4;

    float4 pa0 = *(const float4*)arow0;
    float4 pa1 = *(const float4*)arow1;
    float4 pw0 = *(const float4*)wrow0;
    float4 pw1 = *(const float4*)wrow1;

    const int nkb = K / GBK;
    for (int kb = 0; kb < nkb; kb++) {
        As[c4 * 4 + 0][r0] = pa0.x; As[c4 * 4 + 1][r0] = pa0.y;
        As[c4 * 4 + 2][r0] = pa0.z; As[c4 * 4 + 3][r0] = pa0.w;
        As[c4 * 4 + 0][r1] = pa1.x; As[c4 * 4 + 1][r1] = pa1.y;
        As[c4 * 4 + 2][r1] = pa1.z; As[c4 * 4 + 3][r1] = pa1.w;
        Ws[c4 * 4 + 0][r0] = pw0.x; Ws[c4 * 4 + 1][r0] = pw0.y;
        Ws[c4 * 4 + 2][r0] = pw0.z; Ws[c4 * 4 + 3][r0] = pw0.w;
        Ws[c4 * 4 + 0][r1] = pw1.x; Ws[c4 * 4 + 1][r1] = pw1.y;
        Ws[c4 * 4 + 2][r1] = pw1.z; Ws[c4 * 4 + 3][r1] = pw1.w;
        __syncthreads();

        if (kb + 1 < nkb) {
            const int k = (kb + 1) * GBK;
            pa0 = *(const float4*)(arow0 + k);
            pa1 = *(const float4*)(arow1 + k);
            pw0 = *(const float4*)(wrow0 + k);
            pw1 = *(const float4*)(wrow1 + k);
        }

#pragma unroll
        for (int kk = 0; kk < GBK; kk++) {
            float4 a0 = *(const float4*)&As[kk][ty * 8];
            float4 a1 = *(const float4*)&As[kk][ty * 8 + 4];
            float4 w0 = *(const float4*)&Ws[kk][tx * 8];
            float4 w1 = *(const float4*)&Ws[kk][tx * 8 + 4];
            const float av[8] = {a0.x, a0.y, a0.z, a0.w, a1.x, a1.y, a1.z, a1.w};
            const float wv[8] = {w0.x, w0.y, w0.z, w0.w, w1.x, w1.y, w1.z, w1.w};
#pragma unroll
            for (int i = 0; i < 8; i++)
#pragma unroll
                for (int j = 0; j < 8; j++) acc[i][j] += av[i] * wv[j];
        }
        __syncthreads();
    }

    float bias[8];
#pragma unroll
    for (int j = 0; j < 8; j++) bias[j] = b1[bn + tx * 8 + j];
    if (b2 != nullptr) {
#pragma unroll
        for (int j = 0; j < 8; j++) bias[j] += b2[bn + tx * 8 + j];
    }
#pragma unroll
    for (int i = 0; i < 8; i++) {
        const size_t row = (size_t)(bm + ty * 8 + i) * N + bn + tx * 8;
        float4 s0 = make_float4(acc[i][0] + bias[0], acc[i][1] + bias[1],
                                acc[i][2] + bias[2], acc[i][3] + bias[3]);
        float4 s1 = make_float4(acc[i][4] + bias[4], acc[i][5] + bias[5],
                                acc[i][6] + bias[6], acc[i][7] + bias[7]);
        *(float4*)&C[row] = s0;
        *(float4*)&C[row + 4] = s1;
    }
}

// ---------------------------------------------------------------------------
// Persistent recurrence scan for one layer (all T steps in one launch).
//   g_out[b,t,j] = relu(g_xin[b,t,j] + sum_k h_prev[b,k] * Whh[j,k])
// Grid (32, 4): CTA tile = 16 batch x 32 cols, 256 threads (8 warps,
// 2/SMSP for latency hiding). Threads split k: half kh=0 covers k4 [0,128),
// kh=1 covers [128,256); each half computes the same 2b x 2j micro-tile with
// fma.rn.f32x2 packed over k; halves combined via a 2KB smem reduction.
// Smem (dynamic, 192.5 KB):
//   Ws[32][1028]  : CTA's Whh slice, K-major (resident whole layer)
//   Hs[256][64]   : h_prev tile [k4][b&1][slot^(k4&7)][4], restaged per step
//                   (tail reused as the split-k reduction buffer)
// ---------------------------------------------------------------------------
#define WS_STRIDE 1028
#define WS_FLOATS (32 * WS_STRIDE)
#define HS_FLOATS (256 * 64)
#define SCAN_SMEM ((WS_FLOATS + HS_FLOATS) * (int)sizeof(float))

__global__ __launch_bounds__(256, 1) void rnn_scan_kernel(
    const float* __restrict__ Whh, const float* __restrict__ hid,
    float* __restrict__ hn)
{
    extern __shared__ float sm[];
    float* Ws = sm;                 // [32][WS_STRIDE]
    float* Hs = sm + WS_FLOATS;     // [256][64]
    float* Rs = Hs;                 // reduction buffer (reuse; 128 float4)

    const int jb  = blockIdx.x * 32;
    const int grp = blockIdx.y;          // batch group 0..3
    const int bb  = grp * 16;
    const int tid = threadIdx.x;
    const int kh   = tid >> 7;           // k-half: 0 or 1
    const int htid = tid & 127;          // id within half
    const int wid2 = htid >> 5;          // warp within half: 0..3
    const int lane = tid & 31;
    const int ty   = lane >> 2;          // 0..7 : b-pair (b0 = 2*ty)
    const int txw  = lane & 3;           // 0..3 : j-pair within warp's 8 cols
    const int jloc = wid2 * 8 + txw * 2;

    // One-time: copy this CTA's Whh slice (K-major, padded rows).
#pragma unroll 4
    for (int idx = tid; idx < 32 * 256; idx += 256) {
        const int j = idx >> 8, k4 = idx & 255;
        float4 w = *(const float4*)&Whh[(size_t)(jb + j) * Hh + k4 * 4];
        *(float4*)&Ws[j * WS_STRIDE + k4 * 4] = w;
    }
    __syncthreads();

    const float* wrow0 = Ws + jloc * WS_STRIDE;
    const float* wrow1 = wrow0 + WS_STRIDE;
    const int k4lo = kh * 128;

    for (int t = 0; t < Tt; t++) {
        // ---- stage h_prev tile (16 x 1024) into swizzled smem ----
        const float* hsrc;
        size_t bstride;
        if (t == 0) { hsrc = hid + (size_t)bb * Hh;                    bstride = Hh; }
        else        { hsrc = g_out + ((size_t)bb * Tt + (t - 1)) * Hh; bstride = (size_t)Tt * Hh; }

#pragma unroll 8
        for (int i = 0; i < 16; i++) {
            const int fid = i * 256 + tid;
            const int b  = fid >> 8;       // 0..15
            const int k4 = fid & 255;      // 0..255
            float4 h4 = *(const float4*)&hsrc[(size_t)b * bstride + k4 * 4];
            const int slot = (b >> 1) ^ (k4 & 7);
            *(float4*)&Hs[k4 * 64 + (b & 1) * 32 + slot * 4] = h4;
        }
        __syncthreads();

        // ---- accumulate my k-half: packed-over-k 2x2 outer product ----
        unsigned long long acc[8];
#pragma unroll
        for (int i = 0; i < 8; i++) acc[i] = 0ULL;   // (+0.f, +0.f)

#pragma unroll 8
        for (int kq = 0; kq < 128; kq++) {
            const int k4 = k4lo + kq;
            const int slot = ty ^ (k4 & 7);
            const float* ap = Hs + k4 * 64 + slot * 4;
            ulonglong2 a0 = *(const ulonglong2*)ap;          // h[b0][4k..4k+3]
            ulonglong2 a1 = *(const ulonglong2*)(ap + 32);   // h[b0+1][...]
            ulonglong2 w0 = *(const ulonglong2*)(wrow0 + k4 * 4);
            ulonglong2 w1 = *(const ulonglong2*)(wrow1 + k4 * 4);
            FFMA2(acc[0], a0.x, w0.x, acc[0]);
            FFMA2(acc[1], a0.y, w0.y, acc[1]);
            FFMA2(acc[2], a0.x, w1.x, acc[2]);
            FFMA2(acc[3], a0.y, w1.y, acc[3]);
            FFMA2(acc[4], a1.x, w0.x, acc[4]);
            FFMA2(acc[5], a1.y, w0.y, acc[5]);
            FFMA2(acc[6], a1.x, w1.x, acc[6]);
            FFMA2(acc[7], a1.y, w1.y, acc[7]);
        }

        // ---- horizontal reduce within half ----
        float2 p[8];
#pragma unroll
        for (int i = 0; i < 8; i++) p[i] = *(float2*)&acc[i];
        float4 mine = make_float4(
            (p[0].x + p[0].y) + (p[1].x + p[1].y),
            (p[2].x + p[2].y) + (p[3].x + p[3].y),
            (p[4].x + p[4].y) + (p[5].x + p[5].y),
            (p[6].x + p[6].y) + (p[7].x + p[7].y));

        // ---- combine k-halves (Hs fully consumed; reuse as Rs) ----
        __syncthreads();
        if (kh == 1) *(float4*)&Rs[htid * 4] = mine;
        __syncthreads();

        if (kh == 0) {
            float4 other = *(const float4*)&Rs[htid * 4];
            const float v00 = mine.x + other.x;
            const float v01 = mine.y + other.y;
            const float v10 = mine.z + other.z;
            const float v11 = mine.w + other.w;

            const int b0g = bb + ty * 2;
            const int j0g = jb + jloc;
            const size_t base0 = ((size_t)b0g * Tt + t) * Hh + j0g;
            const size_t base1 = base0 + (size_t)Tt * Hh;

            float2 x0 = *(const float2*)&g_xin[base0];
            float2 x1 = *(const float2*)&g_xin[base1];
            float2 o0 = make_float2(fmaxf(v00 + x0.x, 0.f), fmaxf(v01 + x0.y, 0.f));
            float2 o1 = make_float2(fmaxf(v10 + x1.x, 0.f), fmaxf(v11 + x1.y, 0.f));
            *(float2*)&g_out[base0] = o0;
            *(float2*)&g_out[base1] = o1;

            if (t == Tt - 1) {   // h_n for this layer
                *(float2*)&hn[(size_t)b0g * Hh + j0g]       = o0;
                *(float2*)&hn[(size_t)(b0g + 1) * Hh + j0g] = o1;
            }
        }

        group_barrier(grp);
    }
}

// ---------------------------------------------------------------------------
extern "C" void kernel_launch(void* const* d_in, const int* in_sizes, int n_in,
                              void* d_out, int out_size)
{
    const float* x      = (const float*)d_in[0];
    const float* hidden = (const float*)d_in[1];
    const float* Wih0   = (const float*)d_in[2];
    const float* Whh0   = (const float*)d_in[3];
    const float* bih0   = (const float*)d_in[4];
    const float* bhh0   = (const float*)d_in[5];
    const float* WihL   = (const float*)d_in[6];
    const float* WhhL   = (const float*)d_in[7];
    const float* bihL   = (const float*)d_in[8];
    const float* bhhL   = (const float*)d_in[9];
    const float* Wfc    = (const float*)d_in[10];
    const float* bfc    = (const float*)d_in[11];
    float* out = (float*)d_out;

    float *xin_p = nullptr, *out_p = nullptr;
    cudaGetSymbolAddress((void**)&xin_p, g_xin);
    cudaGetSymbolAddress((void**)&out_p, g_out);

    cudaFuncSetAttribute(rnn_scan_kernel,
                         cudaFuncAttributeMaxDynamicSharedMemorySize, SCAN_SMEM);

    const dim3 projGrid(Mm / GBM, Hh / GBN);   // 256 x 8
    const dim3 scanGrid(Hh / 32, NGROUP);      // 32 x 4 = 128 CTAs (1/SM)
    float* hn_base = out + (size_t)Bb * Tt * Oo;

    for (int l = 0; l < Ll; l++) {
        const float *Wih, *Whh, *bi, *bh;
        if (l == 0) { Wih = Wih0; Whh = Whh0; bi = bih0; bh = bhh0; }
        else {
            Wih = WihL + (size_t)(l - 1) * Hh * Hh;
            Whh = WhhL + (size_t)(l - 1) * Hh * Hh;
            bi  = bihL + (size_t)(l - 1) * Hh;
            bh  = bhhL + (size_t)(l - 1) * Hh;
        }

        // time-parallel input projection: g_xin = in @ Wih^T + b_ih + b_hh
        if (l == 0)
            gemm_bias_kernel<<<projGrid, 256>>>(x,     Wih, bi, bh, xin_p, Mm, Hh, Ii);
        else
            gemm_bias_kernel<<<projGrid, 256>>>(out_p, Wih, bi, bh, xin_p, Mm, Hh, Hh);

        // persistent scan: all 512 steps in one launch
        rnn_scan_kernel<<<scanGrid, 256, SCAN_SMEM>>>(
            Whh, hidden + (size_t)l * Bb * Hh, hn_base + (size_t)l * Bb * Hh);
    }

    // output projection: out = g_out @ W_fc^T + b_fc
    gemm_bias_kernel<<<dim3(Mm / GBM, Oo / GBN), 256>>>(out_p, Wfc, bfc, nullptr,
                                                        out, Mm, Oo, Hh);
}

// round 8
// speedup vs baseline: 1.2772x; 1.2753x over previous
#include <cuda_runtime.h>

#define Bb 64
#define Tt 512
#define Ii 128
#define Hh 1024
#define Ll 4
#define Oo 128
#define Mm (Bb * Tt)   // 32768

#define NGROUP 4       // independent batch-groups (16 b-rows each)
#define GRP_NBLK 32    // CTAs per group barrier (the j-tiles)

// packed fp32 pair FMA: d.lo = a.lo*b.lo + c.lo ; d.hi = a.hi*b.hi + c.hi
#define FFMA2(d, a, b, c) \
    asm("fma.rn.f32x2 %0, %1, %2, %3;" : "=l"(d) : "l"(a), "l"(b), "l"(c))

// Scratch: input projections and layer output / hidden-state history.
// g_out[b][t][h] holds h_t for the layer being scanned; step t reads row t-1.
__device__ float g_xin[(size_t)Bb * Tt * Hh];
__device__ float g_out[(size_t)Bb * Tt * Hh];

// Per-group software barrier. count returns to 0 after each use; phase is
// monotonic and compared to a locally captured snapshot -> safe across graph
// replays. Spin is bounded so any residency surprise degrades to a wrong
// answer instead of a hung container.
__device__ unsigned g_bar_count[NGROUP];
__device__ volatile unsigned g_bar_phase[NGROUP];

__device__ __forceinline__ void group_barrier(int g)
{
    __threadfence();
    __syncthreads();
    if (threadIdx.x == 0) {
        const unsigned old = g_bar_phase[g];
        if (atomicAdd(&g_bar_count[g], 1u) == GRP_NBLK - 1) {
            g_bar_count[g] = 0;
            __threadfence();
            g_bar_phase[g] = old + 1;
        } else {
            const long long t0 = clock64();
            while (g_bar_phase[g] == old) {
                if (clock64() - t0 > 40000000LL) break;   // escape hatch
            }
        }
        __threadfence();
    }
    __syncthreads();
}

// ---------------------------------------------------------------------------
// GEMM: C[M,N] = A[M,K] @ W[N,K]^T + b1[N] (+ b2[N])
// 256 threads, 128x128 tile, BK=16, 8x8 micro-tile, register-prefetch.
// ---------------------------------------------------------------------------
#define GBM 128
#define GBN 128
#define GBK 16

__global__ __launch_bounds__(256, 1) void gemm_bias_kernel(
    const float* __restrict__ A, const float* __restrict__ W,
    const float* __restrict__ b1, const float* __restrict__ b2,
    float* __restrict__ C, int M, int N, int K)
{
    __shared__ __align__(16) float As[GBK][GBM + 4];
    __shared__ __align__(16) float Ws[GBK][GBN + 4];

    const int bm = blockIdx.x * GBM;
    const int bn = blockIdx.y * GBN;
    const int tid = threadIdx.x;
    const int tx = tid & 15;
    const int ty = tid >> 4;

    float acc[8][8];
#pragma unroll
    for (int i = 0; i < 8; i++)
#pragma unroll
        for (int j = 0; j < 8; j++) acc[i][j] = 0.f;

    const int r0 = tid >> 2;
    const int r1 = r0 + 64;
    const int c4 = tid & 3;

    const float* arow0 = A + (size_t)(bm + r0) * K + c4 * 4;
    const float* arow1 = A + (size_t)(bm + r1) * K + c4 * 4;
    const float* wrow0 = W + (size_t)(bn + r0) * K + c4 * 4;
    const float* wrow1 = W + (size_t)(bn + r1) * K + c4 * 4;

    float4 pa0 = *(const float4*)arow0;
    float4 pa1 = *(const float4*)arow1;
    float4 pw0 = *(const float4*)wrow0;
    float4 pw1 = *(const float4*)wrow1;

    const int nkb = K / GBK;
    for (int kb = 0; kb < nkb; kb++) {
        As[c4 * 4 + 0][r0] = pa0.x; As[c4 * 4 + 1][r0] = pa0.y;
        As[c4 * 4 + 2][r0] = pa0.z; As[c4 * 4 + 3][r0] = pa0.w;
        As[c4 * 4 + 0][r1] = pa1.x; As[c4 * 4 + 1][r1] = pa1.y;
        As[c4 * 4 + 2][r1] = pa1.z; As[c4 * 4 + 3][r1] = pa1.w;
        Ws[c4 * 4 + 0][r0] = pw0.x; Ws[c4 * 4 + 1][r0] = pw0.y;
        Ws[c4 * 4 + 2][r0] = pw0.z; Ws[c4 * 4 + 3][r0] = pw0.w;
        Ws[c4 * 4 + 0][r1] = pw1.x; Ws[c4 * 4 + 1][r1] = pw1.y;
        Ws[c4 * 4 + 2][r1] = pw1.z; Ws[c4 * 4 + 3][r1] = pw1.w;
        __syncthreads();

        if (kb + 1 < nkb) {
            const int k = (kb + 1) * GBK;
            pa0 = *(const float4*)(arow0 + k);
            pa1 = *(const float4*)(arow1 + k);
            pw0 = *(const float4*)(wrow0 + k);
            pw1 = *(const float4*)(wrow1 + k);
        }

#pragma unroll
        for (int kk = 0; kk < GBK; kk++) {
            float4 a0 = *(const float4*)&As[kk][ty * 8];
            float4 a1 = *(const float4*)&As[kk][ty * 8 + 4];
            float4 w0 = *(const float4*)&Ws[kk][tx * 8];
            float4 w1 = *(const float4*)&Ws[kk][tx * 8 + 4];
            const float av[8] = {a0.x, a0.y, a0.z, a0.w, a1.x, a1.y, a1.z, a1.w};
            const float wv[8] = {w0.x, w0.y, w0.z, w0.w, w1.x, w1.y, w1.z, w1.w};
#pragma unroll
            for (int i = 0; i < 8; i++)
#pragma unroll
                for (int j = 0; j < 8; j++) acc[i][j] += av[i] * wv[j];
        }
        __syncthreads();
    }

    float bias[8];
#pragma unroll
    for (int j = 0; j < 8; j++) bias[j] = b1[bn + tx * 8 + j];
    if (b2 != nullptr) {
#pragma unroll
        for (int j = 0; j < 8; j++) bias[j] += b2[bn + tx * 8 + j];
    }
#pragma unroll
    for (int i = 0; i < 8; i++) {
        const size_t row = (size_t)(bm + ty * 8 + i) * N + bn + tx * 8;
        float4 s0 = make_float4(acc[i][0] + bias[0], acc[i][1] + bias[1],
                                acc[i][2] + bias[2], acc[i][3] + bias[3]);
        float4 s1 = make_float4(acc[i][4] + bias[4], acc[i][5] + bias[5],
                                acc[i][6] + bias[6], acc[i][7] + bias[7]);
        *(float4*)&C[row] = s0;
        *(float4*)&C[row + 4] = s1;
    }
}

// ---------------------------------------------------------------------------
// Persistent recurrence scan, W-IN-REGISTERS version.
//   g_out[b,t,j] = relu(g_xin[b,t,j] + sum_k h_prev[b,k] * Whh[j,k])
// Grid (32, 4): CTA tile = 16 batch x 32 cols, 256 threads.
// Thread (jg = warp 0..7, kc = lane 0..31): owns j-cols [jb+4*jg, +4) and
// k-chunk [32*kc, +32), holding Whh[4][32] permanently in 128 registers as
// f32x2 pairs. Per step only h is read from smem (2KB/thread). 32 k-partials
// per output are combined through a conflict-free 33-stride smem reduction,
// in two b-phases (8 rows each) to bound accumulator registers.
// Smem layout (dynamic, ~101KB):
//   Hs[16][544] ull : h pairs, word index b*544 + p*33 + kc (conflict-free
//                     for staging stores and lane=kc reads)
//   Rs[256][33] f32 : reduction buffer, o*33 + i (conflict-free both ways)
// ---------------------------------------------------------------------------
#define HS_WORDS (16 * 544)                       // 8B words
#define RS_FLOATS (256 * 33)
#define SCAN_SMEM (HS_WORDS * 8 + RS_FLOATS * 4)  // 103424 B

__global__ __launch_bounds__(256, 1) void rnn_scan_kernel(
    const float* __restrict__ Whh, const float* __restrict__ hid,
    float* __restrict__ hn)
{
    extern __shared__ __align__(16) char smraw[];
    unsigned long long* Hs = (unsigned long long*)smraw;
    float* Rs = (float*)(smraw + HS_WORDS * 8);

    const int jb  = blockIdx.x * 32;
    const int grp = blockIdx.y;          // batch group 0..3
    const int bb  = grp * 16;
    const int tid = threadIdx.x;
    const int jg  = tid >> 5;            // warp = j-group (4 cols)
    const int kc  = tid & 31;            // lane = k-chunk (32 k = 16 pairs)

    // ---- one-time: this thread's Whh[4 j][16 pairs] into registers ----
    unsigned long long w[4][16];
#pragma unroll
    for (int jj = 0; jj < 4; jj++) {
        const float* wr = Whh + (size_t)(jb + jg * 4 + jj) * Hh + kc * 32;
#pragma unroll
        for (int p = 0; p < 16; p++)
            w[jj][p] = *(const unsigned long long*)(wr + p * 2);
    }

    for (int t = 0; t < Tt; t++) {
        // ---- stage h_prev (16 x 1024 f32 = 16 x 512 pairs) into Hs ----
        const float* hsrc;
        size_t bstride;
        if (t == 0) { hsrc = hid + (size_t)bb * Hh;                    bstride = Hh; }
        else        { hsrc = g_out + ((size_t)bb * Tt + (t - 1)) * Hh; bstride = (size_t)Tt * Hh; }

#pragma unroll
        for (int it = 0; it < 32; it++) {
            const int fid = it * 256 + tid;      // 0..8191
            const int b  = fid >> 9;             // 0..15
            const int P  = fid & 511;            // global pair index
            unsigned long long v =
                *(const unsigned long long*)(hsrc + (size_t)b * bstride + P * 2);
            Hs[b * 544 + (P & 15) * 33 + (P >> 4)] = v;
        }
        __syncthreads();

        // ---- two b-phases of 8 rows each ----
#pragma unroll
        for (int ph = 0; ph < 2; ph++) {
            unsigned long long acc[8][4];
#pragma unroll
            for (int i = 0; i < 8; i++)
#pragma unroll
                for (int j = 0; j < 4; j++) acc[i][j] = 0ULL;

#pragma unroll
            for (int b8 = 0; b8 < 8; b8++) {
                const unsigned long long* hrow =
                    Hs + (ph * 8 + b8) * 544 + kc;
#pragma unroll
                for (int p = 0; p < 16; p++) {
                    const unsigned long long h2 = hrow[p * 33];
                    FFMA2(acc[b8][0], h2, w[0][p], acc[b8][0]);
                    FFMA2(acc[b8][1], h2, w[1][p], acc[b8][1]);
                    FFMA2(acc[b8][2], h2, w[2][p], acc[b8][2]);
                    FFMA2(acc[b8][3], h2, w[3][p], acc[b8][3]);
                }
            }

            __syncthreads();   // ph=1: previous reduce-read must finish
            // write k-partials (horizontal pair-sum first)
#pragma unroll
            for (int b8 = 0; b8 < 8; b8++)
#pragma unroll
                for (int jj = 0; jj < 4; jj++) {
                    float2 pa = *(float2*)&acc[b8][jj];
                    const int o = b8 * 32 + jg * 4 + jj;
                    Rs[o * 33 + kc] = pa.x + pa.y;
                }
            __syncthreads();

            // reduce: one output per thread
            {
                const int o  = tid;
                const int bl = o >> 5;       // 0..7
                const int j  = o & 31;
                const float* rp = Rs + o * 33;
                float s0 = 0.f, s1 = 0.f, s2 = 0.f, s3 = 0.f;
#pragma unroll
                for (int i = 0; i < 32; i += 4) {
                    s0 += rp[i + 0]; s1 += rp[i + 1];
                    s2 += rp[i + 2]; s3 += rp[i + 3];
                }
                const float sum = (s0 + s1) + (s2 + s3);

                const int bg = bb + ph * 8 + bl;
                const int jgl = jb + j;
                const size_t base = ((size_t)bg * Tt + t) * Hh + jgl;
                const float v = fmaxf(sum + g_xin[base], 0.f);
                g_out[base] = v;
                if (t == Tt - 1)
                    hn[(size_t)bg * Hh + jgl] = v;
            }
        }

        group_barrier(grp);
    }
}

// ---------------------------------------------------------------------------
extern "C" void kernel_launch(void* const* d_in, const int* in_sizes, int n_in,
                              void* d_out, int out_size)
{
    const float* x      = (const float*)d_in[0];
    const float* hidden = (const float*)d_in[1];
    const float* Wih0   = (const float*)d_in[2];
    const float* Whh0   = (const float*)d_in[3];
    const float* bih0   = (const float*)d_in[4];
    const float* bhh0   = (const float*)d_in[5];
    const float* WihL   = (const float*)d_in[6];
    const float* WhhL   = (const float*)d_in[7];
    const float* bihL   = (const float*)d_in[8];
    const float* bhhL   = (const float*)d_in[9];
    const float* Wfc    = (const float*)d_in[10];
    const float* bfc    = (const float*)d_in[11];
    float* out = (float*)d_out;

    float *xin_p = nullptr, *out_p = nullptr;
    cudaGetSymbolAddress((void**)&xin_p, g_xin);
    cudaGetSymbolAddress((void**)&out_p, g_out);

    cudaFuncSetAttribute(rnn_scan_kernel,
                         cudaFuncAttributeMaxDynamicSharedMemorySize, SCAN_SMEM);

    const dim3 projGrid(Mm / GBM, Hh / GBN);   // 256 x 8
    const dim3 scanGrid(Hh / 32, NGROUP);      // 32 x 4 = 128 CTAs (1/SM)
    float* hn_base = out + (size_t)Bb * Tt * Oo;

    for (int l = 0; l < Ll; l++) {
        const float *Wih, *Whh, *bi, *bh;
        if (l == 0) { Wih = Wih0; Whh = Whh0; bi = bih0; bh = bhh0; }
        else {
            Wih = WihL + (size_t)(l - 1) * Hh * Hh;
            Whh = WhhL + (size_t)(l - 1) * Hh * Hh;
            bi  = bihL + (size_t)(l - 1) * Hh;
            bh  = bhhL + (size_t)(l - 1) * Hh;
        }

        // time-parallel input projection: g_xin = in @ Wih^T + b_ih + b_hh
        if (l == 0)
            gemm_bias_kernel<<<projGrid, 256>>>(x,     Wih, bi, bh, xin_p, Mm, Hh, Ii);
        else
            gemm_bias_kernel<<<projGrid, 256>>>(out_p, Wih, bi, bh, xin_p, Mm, Hh, Hh);

        // persistent scan: all 512 steps in one launch
        rnn_scan_kernel<<<scanGrid, 256, SCAN_SMEM>>>(
            Whh, hidden + (size_t)l * Bb * Hh, hn_base + (size_t)l * Bb * Hh);
    }

    // output projection: out = g_out @ W_fc^T + b_fc
    gemm_bias_kernel<<<dim3(Mm / GBM, Oo / GBN), 256>>>(out_p, Wfc, bfc, nullptr,
                                                        out, Mm, Oo, Hh);
}

// round 9
// speedup vs baseline: 1.3618x; 1.0662x over previous
#include <cuda_runtime.h>

#define Bb 64
#define Tt 512
#define Ii 128
#define Hh 1024
#define Ll 4
#define Oo 128
#define Mm (Bb * Tt)   // 32768

#define NGROUP 4       // independent batch-groups (16 b-rows each)
#define GRP_NBLK 32    // CTAs per group barrier (the j-tiles)

// packed fp32 pair FMA: d.lo = a.lo*b.lo + c.lo ; d.hi = a.hi*b.hi + c.hi
#define FFMA2(d, a, b, c) \
    asm("fma.rn.f32x2 %0, %1, %2, %3;" : "=l"(d) : "l"(a), "l"(b), "l"(c))

// Scratch: input projections and layer output / hidden-state history.
// g_out[b][t][h] holds h_t for the layer being scanned; step t reads row t-1.
__device__ float g_xin[(size_t)Bb * Tt * Hh];
__device__ float g_out[(size_t)Bb * Tt * Hh];

// Per-group software barrier. count returns to 0 after each use; phase is
// monotonic and compared to a locally captured snapshot -> safe across graph
// replays. Spin is bounded so any residency surprise degrades to a wrong
// answer instead of a hung container.
__device__ unsigned g_bar_count[NGROUP];
__device__ volatile unsigned g_bar_phase[NGROUP];

__device__ __forceinline__ void group_barrier(int g)
{
    __threadfence();
    __syncthreads();
    if (threadIdx.x == 0) {
        const unsigned old = g_bar_phase[g];
        if (atomicAdd(&g_bar_count[g], 1u) == GRP_NBLK - 1) {
            g_bar_count[g] = 0;
            __threadfence();
            g_bar_phase[g] = old + 1;
        } else {
            const long long t0 = clock64();
            while (g_bar_phase[g] == old) {
                if (clock64() - t0 > 40000000LL) break;   // escape hatch
            }
        }
        __threadfence();
    }
    __syncthreads();
}

// ---------------------------------------------------------------------------
// GEMM: C[M,N] = A[M,K] @ W[N,K]^T + b1[N] (+ b2[N])
// 256 threads, 128x128 tile, BK=16, 8x8 micro-tile.
// DOUBLE-BUFFERED smem: compute on buffer cur while next k-block waits in
// registers; store to cur^1; ONE syncthreads per k-block. launch_bounds
// (256,2) caps regs at 128 so 2 CTAs/SM cover each other's sync bubbles.
// ---------------------------------------------------------------------------
#define GBM 128
#define GBN 128
#define GBK 16

__global__ __launch_bounds__(256, 2) void gemm_bias_kernel(
    const float* __restrict__ A, const float* __restrict__ W,
    const float* __restrict__ b1, const float* __restrict__ b2,
    float* __restrict__ C, int M, int N, int K)
{
    __shared__ __align__(16) float As[2][GBK][GBM + 4];
    __shared__ __align__(16) float Ws[2][GBK][GBN + 4];

    const int bm = blockIdx.x * GBM;
    const int bn = blockIdx.y * GBN;
    const int tid = threadIdx.x;
    const int tx = tid & 15;
    const int ty = tid >> 4;

    float acc[8][8];
#pragma unroll
    for (int i = 0; i < 8; i++)
#pragma unroll
        for (int j = 0; j < 8; j++) acc[i][j] = 0.f;

    const int r0 = tid >> 2;        // 0..63
    const int r1 = r0 + 64;
    const int c4 = tid & 3;

    const float* arow0 = A + (size_t)(bm + r0) * K + c4 * 4;
    const float* arow1 = A + (size_t)(bm + r1) * K + c4 * 4;
    const float* wrow0 = W + (size_t)(bn + r0) * K + c4 * 4;
    const float* wrow1 = W + (size_t)(bn + r1) * K + c4 * 4;

    // prologue: kb=0 regs -> smem[0]
    float4 pa0 = *(const float4*)arow0;
    float4 pa1 = *(const float4*)arow1;
    float4 pw0 = *(const float4*)wrow0;
    float4 pw1 = *(const float4*)wrow1;

    As[0][c4 * 4 + 0][r0] = pa0.x; As[0][c4 * 4 + 1][r0] = pa0.y;
    As[0][c4 * 4 + 2][r0] = pa0.z; As[0][c4 * 4 + 3][r0] = pa0.w;
    As[0][c4 * 4 + 0][r1] = pa1.x; As[0][c4 * 4 + 1][r1] = pa1.y;
    As[0][c4 * 4 + 2][r1] = pa1.z; As[0][c4 * 4 + 3][r1] = pa1.w;
    Ws[0][c4 * 4 + 0][r0] = pw0.x; Ws[0][c4 * 4 + 1][r0] = pw0.y;
    Ws[0][c4 * 4 + 2][r0] = pw0.z; Ws[0][c4 * 4 + 3][r0] = pw0.w;
    Ws[0][c4 * 4 + 0][r1] = pw1.x; Ws[0][c4 * 4 + 1][r1] = pw1.y;
    Ws[0][c4 * 4 + 2][r1] = pw1.z; Ws[0][c4 * 4 + 3][r1] = pw1.w;
    __syncthreads();

    const int nkb = K / GBK;
    int cur = 0;
    for (int kb = 0; kb < nkb; kb++) {
        // prefetch next k-block into registers (overlaps compute below)
        if (kb + 1 < nkb) {
            const int k = (kb + 1) * GBK;
            pa0 = *(const float4*)(arow0 + k);
            pa1 = *(const float4*)(arow1 + k);
            pw0 = *(const float4*)(wrow0 + k);
            pw1 = *(const float4*)(wrow1 + k);
        }

#pragma unroll
        for (int kk = 0; kk < GBK; kk++) {
            float4 a0 = *(const float4*)&As[cur][kk][ty * 8];
            float4 a1 = *(const float4*)&As[cur][kk][ty * 8 + 4];
            float4 w0 = *(const float4*)&Ws[cur][kk][tx * 8];
            float4 w1 = *(const float4*)&Ws[cur][kk][tx * 8 + 4];
            const float av[8] = {a0.x, a0.y, a0.z, a0.w, a1.x, a1.y, a1.z, a1.w};
            const float wv[8] = {w0.x, w0.y, w0.z, w0.w, w1.x, w1.y, w1.z, w1.w};
#pragma unroll
            for (int i = 0; i < 8; i++)
#pragma unroll
                for (int j = 0; j < 8; j++) acc[i][j] += av[i] * wv[j];
        }

        if (kb + 1 < nkb) {
            const int nxt = cur ^ 1;
            As[nxt][c4 * 4 + 0][r0] = pa0.x; As[nxt][c4 * 4 + 1][r0] = pa0.y;
            As[nxt][c4 * 4 + 2][r0] = pa0.z; As[nxt][c4 * 4 + 3][r0] = pa0.w;
            As[nxt][c4 * 4 + 0][r1] = pa1.x; As[nxt][c4 * 4 + 1][r1] = pa1.y;
            As[nxt][c4 * 4 + 2][r1] = pa1.z; As[nxt][c4 * 4 + 3][r1] = pa1.w;
            Ws[nxt][c4 * 4 + 0][r0] = pw0.x; Ws[nxt][c4 * 4 + 1][r0] = pw0.y;
            Ws[nxt][c4 * 4 + 2][r0] = pw0.z; Ws[nxt][c4 * 4 + 3][r0] = pw0.w;
            Ws[nxt][c4 * 4 + 0][r1] = pw1.x; Ws[nxt][c4 * 4 + 1][r1] = pw1.y;
            Ws[nxt][c4 * 4 + 2][r1] = pw1.z; Ws[nxt][c4 * 4 + 3][r1] = pw1.w;
            __syncthreads();
            cur = nxt;
        }
    }

    float bias[8];
#pragma unroll
    for (int j = 0; j < 8; j++) bias[j] = b1[bn + tx * 8 + j];
    if (b2 != nullptr) {
#pragma unroll
        for (int j = 0; j < 8; j++) bias[j] += b2[bn + tx * 8 + j];
    }
#pragma unroll
    for (int i = 0; i < 8; i++) {
        const size_t row = (size_t)(bm + ty * 8 + i) * N + bn + tx * 8;
        float4 s0 = make_float4(acc[i][0] + bias[0], acc[i][1] + bias[1],
                                acc[i][2] + bias[2], acc[i][3] + bias[3]);
        float4 s1 = make_float4(acc[i][4] + bias[4], acc[i][5] + bias[5],
                                acc[i][6] + bias[6], acc[i][7] + bias[7]);
        *(float4*)&C[row] = s0;
        *(float4*)&C[row + 4] = s1;
    }
}

// ---------------------------------------------------------------------------
// Persistent recurrence scan, W-IN-REGISTERS version (unchanged from R7 win).
//   g_out[b,t,j] = relu(g_xin[b,t,j] + sum_k h_prev[b,k] * Whh[j,k])
// Grid (32, 4): CTA tile = 16 batch x 32 cols, 256 threads.
// Thread (jg = warp 0..7, kc = lane 0..31): owns j-cols [jb+4*jg, +4) and
// k-chunk [32*kc, +32), holding Whh[4][32] permanently in 128 registers as
// f32x2 pairs. Per step only h is read from smem. 32 k-partials per output
// combined via conflict-free 33-stride smem reduction, two b-phases.
// ---------------------------------------------------------------------------
#define HS_WORDS (16 * 544)                       // 8B words
#define RS_FLOATS (256 * 33)
#define SCAN_SMEM (HS_WORDS * 8 + RS_FLOATS * 4)  // 103424 B

__global__ __launch_bounds__(256, 1) void rnn_scan_kernel(
    const float* __restrict__ Whh, const float* __restrict__ hid,
    float* __restrict__ hn)
{
    extern __shared__ __align__(16) char smraw[];
    unsigned long long* Hs = (unsigned long long*)smraw;
    float* Rs = (float*)(smraw + HS_WORDS * 8);

    const int jb  = blockIdx.x * 32;
    const int grp = blockIdx.y;          // batch group 0..3
    const int bb  = grp * 16;
    const int tid = threadIdx.x;
    const int jg  = tid >> 5;            // warp = j-group (4 cols)
    const int kc  = tid & 31;            // lane = k-chunk (32 k = 16 pairs)

    // ---- one-time: this thread's Whh[4 j][16 pairs] into registers ----
    unsigned long long w[4][16];
#pragma unroll
    for (int jj = 0; jj < 4; jj++) {
        const float* wr = Whh + (size_t)(jb + jg * 4 + jj) * Hh + kc * 32;
#pragma unroll
        for (int p = 0; p < 16; p++)
            w[jj][p] = *(const unsigned long long*)(wr + p * 2);
    }

    for (int t = 0; t < Tt; t++) {
        // ---- stage h_prev (16 x 1024 f32 = 16 x 512 pairs) into Hs ----
        const float* hsrc;
        size_t bstride;
        if (t == 0) { hsrc = hid + (size_t)bb * Hh;                    bstride = Hh; }
        else        { hsrc = g_out + ((size_t)bb * Tt + (t - 1)) * Hh; bstride = (size_t)Tt * Hh; }

#pragma unroll
        for (int it = 0; it < 32; it++) {
            const int fid = it * 256 + tid;      // 0..8191
            const int b  = fid >> 9;             // 0..15
            const int P  = fid & 511;            // global pair index
            unsigned long long v =
                *(const unsigned long long*)(hsrc + (size_t)b * bstride + P * 2);
            Hs[b * 544 + (P & 15) * 33 + (P >> 4)] = v;
        }
        __syncthreads();

        // ---- two b-phases of 8 rows each ----
#pragma unroll
        for (int ph = 0; ph < 2; ph++) {
            unsigned long long acc[8][4];
#pragma unroll
            for (int i = 0; i < 8; i++)
#pragma unroll
                for (int j = 0; j < 4; j++) acc[i][j] = 0ULL;

#pragma unroll
            for (int b8 = 0; b8 < 8; b8++) {
                const unsigned long long* hrow =
                    Hs + (ph * 8 + b8) * 544 + kc;
#pragma unroll
                for (int p = 0; p < 16; p++) {
                    const unsigned long long h2 = hrow[p * 33];
                    FFMA2(acc[b8][0], h2, w[0][p], acc[b8][0]);
                    FFMA2(acc[b8][1], h2, w[1][p], acc[b8][1]);
                    FFMA2(acc[b8][2], h2, w[2][p], acc[b8][2]);
                    FFMA2(acc[b8][3], h2, w[3][p], acc[b8][3]);
                }
            }

            __syncthreads();   // ph=1: previous reduce-read must finish
            // write k-partials (horizontal pair-sum first)
#pragma unroll
            for (int b8 = 0; b8 < 8; b8++)
#pragma unroll
                for (int jj = 0; jj < 4; jj++) {
                    float2 pa = *(float2*)&acc[b8][jj];
                    const int o = b8 * 32 + jg * 4 + jj;
                    Rs[o * 33 + kc] = pa.x + pa.y;
                }
            __syncthreads();

            // reduce: one output per thread
            {
                const int o  = tid;
                const int bl = o >> 5;       // 0..7
                const int j  = o & 31;
                const float* rp = Rs + o * 33;
                float s0 = 0.f, s1 = 0.f, s2 = 0.f, s3 = 0.f;
#pragma unroll
                for (int i = 0; i < 32; i += 4) {
                    s0 += rp[i + 0]; s1 += rp[i + 1];
                    s2 += rp[i + 2]; s3 += rp[i + 3];
                }
                const float sum = (s0 + s1) + (s2 + s3);

                const int bg = bb + ph * 8 + bl;
                const int jgl = jb + j;
                const size_t base = ((size_t)bg * Tt + t) * Hh + jgl;
                const float v = fmaxf(sum + g_xin[base], 0.f);
                g_out[base] = v;
                if (t == Tt - 1)
                    hn[(size_t)bg * Hh + jgl] = v;
            }
        }

        group_barrier(grp);
    }
}

// ---------------------------------------------------------------------------
extern "C" void kernel_launch(void* const* d_in, const int* in_sizes, int n_in,
                              void* d_out, int out_size)
{
    const float* x      = (const float*)d_in[0];
    const float* hidden = (const float*)d_in[1];
    const float* Wih0   = (const float*)d_in[2];
    const float* Whh0   = (const float*)d_in[3];
    const float* bih0   = (const float*)d_in[4];
    const float* bhh0   = (const float*)d_in[5];
    const float* WihL   = (const float*)d_in[6];
    const float* WhhL   = (const float*)d_in[7];
    const float* bihL   = (const float*)d_in[8];
    const float* bhhL   = (const float*)d_in[9];
    const float* Wfc    = (const float*)d_in[10];
    const float* bfc    = (const float*)d_in[11];
    float* out = (float*)d_out;

    float *xin_p = nullptr, *out_p = nullptr;
    cudaGetSymbolAddress((void**)&xin_p, g_xin);
    cudaGetSymbolAddress((void**)&out_p, g_out);

    cudaFuncSetAttribute(rnn_scan_kernel,
                         cudaFuncAttributeMaxDynamicSharedMemorySize, SCAN_SMEM);

    const dim3 projGrid(Mm / GBM, Hh / GBN);   // 256 x 8
    const dim3 scanGrid(Hh / 32, NGROUP);      // 32 x 4 = 128 CTAs (1/SM)
    float* hn_base = out + (size_t)Bb * Tt * Oo;

    for (int l = 0; l < Ll; l++) {
        const float *Wih, *Whh, *bi, *bh;
        if (l == 0) { Wih = Wih0; Whh = Whh0; bi = bih0; bh = bhh0; }
        else {
            Wih = WihL + (size_t)(l - 1) * Hh * Hh;
            Whh = WhhL + (size_t)(l - 1) * Hh * Hh;
            bi  = bihL + (size_t)(l - 1) * Hh;
            bh  = bhhL + (size_t)(l - 1) * Hh;
        }

        // time-parallel input projection: g_xin = in @ Wih^T + b_ih + b_hh
        if (l == 0)
            gemm_bias_kernel<<<projGrid, 256>>>(x,     Wih, bi, bh, xin_p, Mm, Hh, Ii);
        else
            gemm_bias_kernel<<<projGrid, 256>>>(out_p, Wih, bi, bh, xin_p, Mm, Hh, Hh);

        // persistent scan: all 512 steps in one launch
        rnn_scan_kernel<<<scanGrid, 256, SCAN_SMEM>>>(
            Whh, hidden + (size_t)l * Bb * Hh, hn_base + (size_t)l * Bb * Hh);
    }

    // output projection: out = g_out @ W_fc^T + b_fc
    gemm_bias_kernel<<<dim3(Mm / GBM, Oo / GBN), 256>>>(out_p, Wfc, bfc, nullptr,
                                                        out, Mm, Oo, Hh);
}

// round 11
// speedup vs baseline: 1.5189x; 1.1154x over previous
#include <cuda_runtime.h>
#include <cstdint>

#define Bb 64
#define Tt 512
#define Ii 128
#define Hh 1024
#define Ll 4
#define Oo 128
#define Mm (Bb * Tt)   // 32768

#define NGROUP 4       // independent batch-groups (16 b-rows each)
#define GRP_NBLK 32    // CTAs per group barrier (the j-tiles)

// packed fp32 pair FMA: d.lo = a.lo*b.lo + c.lo ; d.hi = a.hi*b.hi + c.hi
#define FFMA2(d, a, b, c) \
    asm("fma.rn.f32x2 %0, %1, %2, %3;" : "=l"(d) : "l"(a), "l"(b), "l"(c))

// bf16 tensor-core mma: D(4xf32) += A(4x.b32 bf16x2) * B(2x.b32 bf16x2)
#define MMA_BF16(c, a, b) \
    asm("mma.sync.aligned.m16n8k16.row.col.f32.bf16.bf16.f32 " \
        "{%0,%1,%2,%3}, {%4,%5,%6,%7}, {%8,%9}, {%0,%1,%2,%3};" \
        : "+f"((c)[0]), "+f"((c)[1]), "+f"((c)[2]), "+f"((c)[3]) \
        : "r"((a)[0]), "r"((a)[1]), "r"((a)[2]), "r"((a)[3]), \
          "r"((b)[0]), "r"((b)[1]))

#define LDSM_X4(r, addr) \
    asm("ldmatrix.sync.aligned.m8n8.x4.shared.b16 {%0,%1,%2,%3}, [%4];" \
        : "=r"((r)[0]), "=r"((r)[1]), "=r"((r)[2]), "=r"((r)[3]) \
        : "r"(addr))

// Scratch: input projections and layer output / hidden-state history.
__device__ float g_xin[(size_t)Bb * Tt * Hh];
__device__ float g_out[(size_t)Bb * Tt * Hh];

// Per-group software barrier (bounded spin; monotonic phase -> replay-safe).
__device__ unsigned g_bar_count[NGROUP];
__device__ volatile unsigned g_bar_phase[NGROUP];

__device__ __forceinline__ void group_barrier(int g)
{
    __threadfence();
    __syncthreads();
    if (threadIdx.x == 0) {
        const unsigned old = g_bar_phase[g];
        if (atomicAdd(&g_bar_count[g], 1u) == GRP_NBLK - 1) {
            g_bar_count[g] = 0;
            __threadfence();
            g_bar_phase[g] = old + 1;
        } else {
            const long long t0 = clock64();
            while (g_bar_phase[g] == old) {
                if (clock64() - t0 > 40000000LL) break;   // escape hatch
            }
        }
        __threadfence();
    }
    __syncthreads();
}

// ---------------------------------------------------------------------------
// Tensor-core GEMM with bf16 hi/lo split (3-term, ~2^-16 precision):
//   C[M,N] = A[M,K] @ W[N,K]^T + b1[N] (+ b2[N])
// 256 threads = 8 warps (2x4), CTA tile 128x128, BK=32, warp tile 64x32.
// f32 tiles are converted to (hi, lo) bf16 in the smem loader. A fragments
// via ldmatrix.x4; B fragments are direct .b32 reads of W's [n][k] rows
// (exactly mma.col layout). Double-buffered, one syncthreads per k-block.
// smem row stride 40 bf16 (80 B): banks r*20 mod 32 all-distinct ->
// conflict-free ldmatrix and B reads.
// ---------------------------------------------------------------------------
#define GSTRIDE 40                       // bf16 units per smem row
#define GTILE_B (128 * GSTRIDE * 2)      // 10240 B per tile buffer
#define GAH_OFF 0
#define GAL_OFF (2 * GTILE_B)
#define GWH_OFF (4 * GTILE_B)
#define GWL_OFF (6 * GTILE_B)
#define GEMM_SMEM (8 * GTILE_B)          // 81920 B

__device__ __forceinline__ void cvt_hilo_store(uint32_t* hi_p, uint32_t* lo_p,
                                               float4 v)
{
    uint32_t h0, h1, l0, l1;
    asm("cvt.rn.bf16x2.f32 %0, %1, %2;" : "=r"(h0) : "f"(v.y), "f"(v.x));
    asm("cvt.rn.bf16x2.f32 %0, %1, %2;" : "=r"(h1) : "f"(v.w), "f"(v.z));
    const float rx = v.x - __uint_as_float(h0 << 16);
    const float ry = v.y - __uint_as_float(h0 & 0xffff0000u);
    const float rz = v.z - __uint_as_float(h1 << 16);
    const float rw = v.w - __uint_as_float(h1 & 0xffff0000u);
    asm("cvt.rn.bf16x2.f32 %0, %1, %2;" : "=r"(l0) : "f"(ry), "f"(rx));
    asm("cvt.rn.bf16x2.f32 %0, %1, %2;" : "=r"(l1) : "f"(rw), "f"(rz));
    hi_p[0] = h0; hi_p[1] = h1;
    lo_p[0] = l0; lo_p[1] = l1;
}

__global__ __launch_bounds__(256, 1) void gemm_bias_kernel(
    const float* __restrict__ A, const float* __restrict__ W,
    const float* __restrict__ b1, const float* __restrict__ b2,
    float* __restrict__ C, int M, int N, int K)
{
    extern __shared__ __align__(16) char gsm[];
    uint16_t* sm16 = (uint16_t*)gsm;
    const uint32_t sbase = (uint32_t)__cvta_generic_to_shared(gsm);

    const int bm = blockIdx.x * 128;
    const int bn = blockIdx.y * 128;
    const int tid = threadIdx.x;
    const int wid = tid >> 5;
    const int lane = tid & 31;
    const int warpM = (wid >> 2) * 64;
    const int warpN = (wid & 3) * 32;
    const int lrowA = lane & 15;          // ldmatrix row within m16 tile
    const int lcol8 = (lane >> 4) * 8;    // ldmatrix k-half select
    const int bnrow = lane >> 2;          // B fragment n within n8 tile
    const int bk2   = (lane & 3) * 2;     // B fragment k pair

    // loader mapping: thread -> (row, k-half of 16)
    const int lrow  = tid >> 1;           // 0..127
    const int lhalf = tid & 1;            // 0/1 -> k 0-15 / 16-31
    const float* aptr = A + (size_t)(bm + lrow) * K + lhalf * 16;
    const float* wptr = W + (size_t)(bn + lrow) * K + lhalf * 16;
    const int sidx = lrow * GSTRIDE + lhalf * 16;   // bf16 units

    float c[4][4][4];
#pragma unroll
    for (int mt = 0; mt < 4; mt++)
#pragma unroll
        for (int nt = 0; nt < 4; nt++)
#pragma unroll
            for (int i = 0; i < 4; i++) c[mt][nt][i] = 0.f;

    // prologue: k-block 0 -> buffers[0]
    float4 fa[4], fw[4];
#pragma unroll
    for (int q = 0; q < 4; q++) {
        fa[q] = *(const float4*)(aptr + q * 4);
        fw[q] = *(const float4*)(wptr + q * 4);
    }
#pragma unroll
    for (int q = 0; q < 4; q++) {
        cvt_hilo_store((uint32_t*)&sm16[(GAH_OFF >> 1) + sidx + q * 4],
                       (uint32_t*)&sm16[(GAL_OFF >> 1) + sidx + q * 4], fa[q]);
        cvt_hilo_store((uint32_t*)&sm16[(GWH_OFF >> 1) + sidx + q * 4],
                       (uint32_t*)&sm16[(GWL_OFF >> 1) + sidx + q * 4], fw[q]);
    }
    __syncthreads();

    const int nkb = K / 32;
    int cur = 0;
    for (int kb = 0; kb < nkb; kb++) {
        if (kb + 1 < nkb) {
            const int k = (kb + 1) * 32;
#pragma unroll
            for (int q = 0; q < 4; q++) {
                fa[q] = *(const float4*)(aptr + k + q * 4);
                fw[q] = *(const float4*)(wptr + k + q * 4);
            }
        }

        const uint32_t ah_b = sbase + GAH_OFF + cur * GTILE_B;
        const uint32_t al_b = sbase + GAL_OFF + cur * GTILE_B;
        const int wh_e = ((GWH_OFF + cur * GTILE_B) >> 1);
        const int wl_e = ((GWL_OFF + cur * GTILE_B) >> 1);

#pragma unroll
        for (int k16 = 0; k16 < 2; k16++) {
            const int koff = k16 * 16;
            uint32_t ah[4][4], al[4][4];
#pragma unroll
            for (int mt = 0; mt < 4; mt++) {
                const uint32_t ro =
                    ((warpM + mt * 16 + lrowA) * GSTRIDE + koff + lcol8) * 2;
                LDSM_X4(ah[mt], ah_b + ro);
                LDSM_X4(al[mt], al_b + ro);
            }
            uint32_t bh[4][2], bl[4][2];
#pragma unroll
            for (int nt = 0; nt < 4; nt++) {
                const int idx =
                    (warpN + nt * 8 + bnrow) * GSTRIDE + koff + bk2;
                bh[nt][0] = *(const uint32_t*)&sm16[wh_e + idx];
                bh[nt][1] = *(const uint32_t*)&sm16[wh_e + idx + 8];
                bl[nt][0] = *(const uint32_t*)&sm16[wl_e + idx];
                bl[nt][1] = *(const uint32_t*)&sm16[wl_e + idx + 8];
            }
#pragma unroll
            for (int mt = 0; mt < 4; mt++)
#pragma unroll
                for (int nt = 0; nt < 4; nt++) {
                    MMA_BF16(c[mt][nt], ah[mt], bh[nt]);   // hi*hi
                    MMA_BF16(c[mt][nt], ah[mt], bl[nt]);   // hi*lo
                    MMA_BF16(c[mt][nt], al[mt], bh[nt]);   // lo*hi
                }
        }

        if (kb + 1 < nkb) {
            const int nxt = cur ^ 1;
            const int ah_e = ((GAH_OFF + nxt * GTILE_B) >> 1);
            const int al_e = ((GAL_OFF + nxt * GTILE_B) >> 1);
            const int wh_e2 = ((GWH_OFF + nxt * GTILE_B) >> 1);
            const int wl_e2 = ((GWL_OFF + nxt * GTILE_B) >> 1);
#pragma unroll
            for (int q = 0; q < 4; q++) {
                cvt_hilo_store((uint32_t*)&sm16[ah_e + sidx + q * 4],
                               (uint32_t*)&sm16[al_e + sidx + q * 4], fa[q]);
                cvt_hilo_store((uint32_t*)&sm16[wh_e2 + sidx + q * 4],
                               (uint32_t*)&sm16[wl_e2 + sidx + q * 4], fw[q]);
            }
            __syncthreads();
            cur = nxt;
        }
    }

    // epilogue: bias + store (fragment rows lane>>2 / +8, cols (lane&3)*2)
#pragma unroll
    for (int nt = 0; nt < 4; nt++) {
        const int col = bn + warpN + nt * 8 + bk2;
        float bx = b1[col], by = b1[col + 1];
        if (b2 != nullptr) { bx += b2[col]; by += b2[col + 1]; }
#pragma unroll
        for (int mt = 0; mt < 4; mt++) {
            const int row = bm + warpM + mt * 16 + (lane >> 2);
            float2 s0 = make_float2(c[mt][nt][0] + bx, c[mt][nt][1] + by);
            float2 s1 = make_float2(c[mt][nt][2] + bx, c[mt][nt][3] + by);
            *(float2*)&C[(size_t)row * N + col] = s0;
            *(float2*)&C[(size_t)(row + 8) * N + col] = s1;
        }
    }
}

// ---------------------------------------------------------------------------
// Persistent recurrence scan, W-IN-REGISTERS (unchanged from R7/R8 win).
//   g_out[b,t,j] = relu(g_xin[b,t,j] + sum_k h_prev[b,k] * Whh[j,k])
// ---------------------------------------------------------------------------
#define HS_WORDS (16 * 544)                       // 8B words
#define RS_FLOATS (256 * 33)
#define SCAN_SMEM (HS_WORDS * 8 + RS_FLOATS * 4)  // 103424 B

__global__ __launch_bounds__(256, 1) void rnn_scan_kernel(
    const float* __restrict__ Whh, const float* __restrict__ hid,
    float* __restrict__ hn)
{
    extern __shared__ __align__(16) char smraw[];
    unsigned long long* Hs = (unsigned long long*)smraw;
    float* Rs = (float*)(smraw + HS_WORDS * 8);

    const int jb  = blockIdx.x * 32;
    const int grp = blockIdx.y;          // batch group 0..3
    const int bb  = grp * 16;
    const int tid = threadIdx.x;
    const int jg  = tid >> 5;            // warp = j-group (4 cols)
    const int kc  = tid & 31;            // lane = k-chunk (32 k = 16 pairs)

    unsigned long long w[4][16];
#pragma unroll
    for (int jj = 0; jj < 4; jj++) {
        const float* wr = Whh + (size_t)(jb + jg * 4 + jj) * Hh + kc * 32;
#pragma unroll
        for (int p = 0; p < 16; p++)
            w[jj][p] = *(const unsigned long long*)(wr + p * 2);
    }

    for (int t = 0; t < Tt; t++) {
        const float* hsrc;
        size_t bstride;
        if (t == 0) { hsrc = hid + (size_t)bb * Hh;                    bstride = Hh; }
        else        { hsrc = g_out + ((size_t)bb * Tt + (t - 1)) * Hh; bstride = (size_t)Tt * Hh; }

#pragma unroll
        for (int it = 0; it < 32; it++) {
            const int fid = it * 256 + tid;
            const int b  = fid >> 9;
            const int P  = fid & 511;
            unsigned long long v =
                *(const unsigned long long*)(hsrc + (size_t)b * bstride + P * 2);
            Hs[b * 544 + (P & 15) * 33 + (P >> 4)] = v;
        }
        __syncthreads();

#pragma unroll
        for (int ph = 0; ph < 2; ph++) {
            unsigned long long acc[8][4];
#pragma unroll
            for (int i = 0; i < 8; i++)
#pragma unroll
                for (int j = 0; j < 4; j++) acc[i][j] = 0ULL;

#pragma unroll
            for (int b8 = 0; b8 < 8; b8++) {
                const unsigned long long* hrow =
                    Hs + (ph * 8 + b8) * 544 + kc;
#pragma unroll
                for (int p = 0; p < 16; p++) {
                    const unsigned long long h2 = hrow[p * 33];
                    FFMA2(acc[b8][0], h2, w[0][p], acc[b8][0]);
                    FFMA2(acc[b8][1], h2, w[1][p], acc[b8][1]);
                    FFMA2(acc[b8][2], h2, w[2][p], acc[b8][2]);
                    FFMA2(acc[b8][3], h2, w[3][p], acc[b8][3]);
                }
            }

            __syncthreads();
#pragma unroll
            for (int b8 = 0; b8 < 8; b8++)
#pragma unroll
                for (int jj = 0; jj < 4; jj++) {
                    float2 pa = *(float2*)&acc[b8][jj];
                    const int o = b8 * 32 + jg * 4 + jj;
                    Rs[o * 33 + kc] = pa.x + pa.y;
                }
            __syncthreads();

            {
                const int o  = tid;
                const int bl = o >> 5;
                const int j  = o & 31;
                const float* rp = Rs + o * 33;
                float s0 = 0.f, s1 = 0.f, s2 = 0.f, s3 = 0.f;
#pragma unroll
                for (int i = 0; i < 32; i += 4) {
                    s0 += rp[i + 0]; s1 += rp[i + 1];
                    s2 += rp[i + 2]; s3 += rp[i + 3];
                }
                const float sum = (s0 + s1) + (s2 + s3);

                const int bg = bb + ph * 8 + bl;
                const int jgl = jb + j;
                const size_t base = ((size_t)bg * Tt + t) * Hh + jgl;
                const float v = fmaxf(sum + g_xin[base], 0.f);
                g_out[base] = v;
                if (t == Tt - 1)
                    hn[(size_t)bg * Hh + jgl] = v;
            }
        }

        group_barrier(grp);
    }
}

// ---------------------------------------------------------------------------
extern "C" void kernel_launch(void* const* d_in, const int* in_sizes, int n_in,
                              void* d_out, int out_size)
{
    const float* x      = (const float*)d_in[0];
    const float* hidden = (const float*)d_in[1];
    const float* Wih0   = (const float*)d_in[2];
    const float* Whh0   = (const float*)d_in[3];
    const float* bih0   = (const float*)d_in[4];
    const float* bhh0   = (const float*)d_in[5];
    const float* WihL   = (const float*)d_in[6];
    const float* WhhL   = (const float*)d_in[7];
    const float* bihL   = (const float*)d_in[8];
    const float* bhhL   = (const float*)d_in[9];
    const float* Wfc    = (const float*)d_in[10];
    const float* bfc    = (const float*)d_in[11];
    float* out = (float*)d_out;

    float *xin_p = nullptr, *out_p = nullptr;
    cudaGetSymbolAddress((void**)&xin_p, g_xin);
    cudaGetSymbolAddress((void**)&out_p, g_out);

    cudaFuncSetAttribute(rnn_scan_kernel,
                         cudaFuncAttributeMaxDynamicSharedMemorySize, SCAN_SMEM);
    cudaFuncSetAttribute(gemm_bias_kernel,
                         cudaFuncAttributeMaxDynamicSharedMemorySize, GEMM_SMEM);

    const dim3 projGrid(Mm / 128, Hh / 128);   // 256 x 8
    const dim3 scanGrid(Hh / 32, NGROUP);      // 32 x 4 = 128 CTAs (1/SM)
    float* hn_base = out + (size_t)Bb * Tt * Oo;

    for (int l = 0; l < Ll; l++) {
        const float *Wih, *Whh, *bi, *bh;
        if (l == 0) { Wih = Wih0; Whh = Whh0; bi = bih0; bh = bhh0; }
        else {
            Wih = WihL + (size_t)(l - 1) * Hh * Hh;
            Whh = WhhL + (size_t)(l - 1) * Hh * Hh;
            bi  = bihL + (size_t)(l - 1) * Hh;
            bh  = bhhL + (size_t)(l - 1) * Hh;
        }

        // time-parallel input projection: g_xin = in @ Wih^T + b_ih + b_hh
        if (l == 0)
            gemm_bias_kernel<<<projGrid, 256, GEMM_SMEM>>>(
                x, Wih, bi, bh, xin_p, Mm, Hh, Ii);
        else
            gemm_bias_kernel<<<projGrid, 256, GEMM_SMEM>>>(
                out_p, Wih, bi, bh, xin_p, Mm, Hh, Hh);

        // persistent scan: all 512 steps in one launch
        rnn_scan_kernel<<<scanGrid, 256, SCAN_SMEM>>>(
            Whh, hidden + (size_t)l * Bb * Hh, hn_base + (size_t)l * Bb * Hh);
    }

    // output projection: out = g_out @ W_fc^T + b_fc
    gemm_bias_kernel<<<dim3(Mm / 128, Oo / 128), 256, GEMM_SMEM>>>(
        out_p, Wfc, bfc, nullptr, out, Mm, Oo, Hh);
}